// round 12
// baseline (speedup 1.0000x reference)
#include <cuda_runtime.h>

// Tree DP on deterministic 4-ary heap: L=4096, B=64, C=2.
// msg[b,cs,k] = lse_{cj}( E[b,cj,j] + msg[b,cj,j] + T[k,j,cs,cj] ), j=(k-1)>>2.
//
// Warp-autonomous, zero barriers / zero smem. Each WARP owns (subtree r in
// [21,85), FOUR batches): T lines + index math amortized 4x. Grid 64x2 = 128
// blocks, 1024 warps. Parent locals propagate via shfl; all loads issued up
// front (one DRAM wave, high per-warp MLP). 2-batch version measured 6.40us;
// this pushes the instruction-amortization lever one more notch.

#define LN  4096
#define CLN 8192
#define NB  4

__device__ __forceinline__ float lse2(float a, float b) {
    float mx = fmaxf(a, b);
    float mn = fminf(a, b);
    return mx + __logf(1.0f + __expf(mn - mx));
}

__global__ void __launch_bounds__(256, 1)
k_all(const float* __restrict__ E, const float* __restrict__ T, float* __restrict__ M)
{
    const int lane = threadIdx.x & 31;
    const int w    = threadIdx.x >> 5;
    const int r    = 21 + blockIdx.x;               // subtree root, [21,85)
    const int b0   = (blockIdx.y * 8 + w) * NB;     // batches b0..b0+3

    const int p2 = (r - 1) >> 2;
    const int p1 = (p2 - 1) >> 2;

    const float4* __restrict__ T4 = (const float4*)T;

    const float* Eb[NB];
    float*       Mb[NB];
    #pragma unroll
    for (int i = 0; i < NB; ++i) {
        Eb[i] = E + (b0 + i) * CLN;
        Mb[i] = M + (b0 + i) * CLN;
    }

    // ---------------- prefetch (static indices, one DRAM wave) --------------
    float4 tA = __ldg(T4 + p1 * LN + 0);
    float4 tB = __ldg(T4 + p2 * LN + p1);
    float4 tC = __ldg(T4 + r  * LN + p2);

    float eR[NB][2], e1[NB][2], e2[NB][2], er[NB][2];
    #pragma unroll
    for (int i = 0; i < NB; ++i) {
        eR[i][0] = Eb[i][0];   eR[i][1] = Eb[i][LN];
        e1[i][0] = Eb[i][p1];  e1[i][1] = Eb[i][LN + p1];
        e2[i][0] = Eb[i][p2];  e2[i][1] = Eb[i][LN + p2];
        er[i][0] = Eb[i][r];   er[i][1] = Eb[i][LN + r];
    }

    // level 3: node n3 = lane&3 (shfl sources: lanes 0-3)
    const int n3 = lane & 3;
    const int k3 = 4 * r + 1 + n3;
    float4 t3 = __ldg(T4 + k3 * LN + r);
    float e3[NB][2] = {};
    if (lane < 4) {
        #pragma unroll
        for (int i = 0; i < NB; ++i) { e3[i][0] = Eb[i][k3];  e3[i][1] = Eb[i][LN + k3]; }
    }

    // level 4: node n4 = lane&15 (shfl sources: lanes 0-15)
    const int n4 = lane & 15;
    const int k4 = 16 * r + 5 + n4;
    float4 t4 = __ldg(T4 + k4 * LN + ((k4 - 1) >> 2));
    float e4[NB][2] = {};
    if (lane < 16) {
        #pragma unroll
        for (int i = 0; i < NB; ++i) { e4[i][0] = Eb[i][k4];  e4[i][1] = Eb[i][LN + k4]; }
    }

    // level 5 (leaves, no E needed): nodes lane and lane+32
    const int k5a = 64 * r + 21 + lane;
    const int k5b = k5a + 32;
    const bool va = (k5a < LN), vb = (k5b < LN);
    float4 t5a, t5b;
    if (va) t5a = __ldg(T4 + k5a * LN + ((k5a - 1) >> 2));
    if (vb) t5b = __ldg(T4 + k5b * LN + ((k5b - 1) >> 2));

    // node 0 never receives a message -> zero (output poisoned); one writer group
    if (blockIdx.x == 0 && lane < 2) {
        #pragma unroll
        for (int i = 0; i < NB; ++i) Mb[i][lane * LN] = 0.0f;
    }

    // ---------------- path root -> p1 -> p2 -> r (all lanes, NB batches) ----
    float m[NB][2], l[NB][2];
    #pragma unroll
    for (int i = 0; i < NB; ++i) {
        m[i][0] = lse2(eR[i][0] + tA.x, eR[i][1] + tA.y);
        m[i][1] = lse2(eR[i][0] + tA.z, eR[i][1] + tA.w);
    }
    if (lane == 0) {
        #pragma unroll
        for (int i = 0; i < NB; ++i) { Mb[i][p1] = m[i][0];  Mb[i][LN + p1] = m[i][1]; }
    }
    #pragma unroll
    for (int i = 0; i < NB; ++i) {
        l[i][0] = e1[i][0] + m[i][0];  l[i][1] = e1[i][1] + m[i][1];
        m[i][0] = lse2(l[i][0] + tB.x, l[i][1] + tB.y);
        m[i][1] = lse2(l[i][0] + tB.z, l[i][1] + tB.w);
    }
    if (lane == 0) {
        #pragma unroll
        for (int i = 0; i < NB; ++i) { Mb[i][p2] = m[i][0];  Mb[i][LN + p2] = m[i][1]; }
    }
    #pragma unroll
    for (int i = 0; i < NB; ++i) {
        l[i][0] = e2[i][0] + m[i][0];  l[i][1] = e2[i][1] + m[i][1];
        m[i][0] = lse2(l[i][0] + tC.x, l[i][1] + tC.y);
        m[i][1] = lse2(l[i][0] + tC.z, l[i][1] + tC.w);
    }
    if (lane == 0) {
        #pragma unroll
        for (int i = 0; i < NB; ++i) { Mb[i][r] = m[i][0];   Mb[i][LN + r] = m[i][1]; }
    }
    float lr[NB][2];
    #pragma unroll
    for (int i = 0; i < NB; ++i) {
        lr[i][0] = er[i][0] + m[i][0];  lr[i][1] = er[i][1] + m[i][1];
    }

    // ---------------- level 3 (4 nodes; lane holds node lane&3) -------------
    float m3[NB][2], l3[NB][2];
    #pragma unroll
    for (int i = 0; i < NB; ++i) {
        m3[i][0] = lse2(lr[i][0] + t3.x, lr[i][1] + t3.y);
        m3[i][1] = lse2(lr[i][0] + t3.z, lr[i][1] + t3.w);
    }
    if (lane < 4) {
        #pragma unroll
        for (int i = 0; i < NB; ++i) { Mb[i][k3] = m3[i][0];  Mb[i][LN + k3] = m3[i][1]; }
    }
    #pragma unroll
    for (int i = 0; i < NB; ++i) {
        l3[i][0] = e3[i][0] + m3[i][0];  l3[i][1] = e3[i][1] + m3[i][1];
    }

    // ---------------- level 4 (16 nodes; lane holds node lane&15) -----------
    const int s4 = n4 >> 2;
    float m4[NB][2], l4[NB][2];
    #pragma unroll
    for (int i = 0; i < NB; ++i) {
        float p0 = __shfl_sync(0xffffffffu, l3[i][0], s4);
        float p1v = __shfl_sync(0xffffffffu, l3[i][1], s4);
        m4[i][0] = lse2(p0 + t4.x, p1v + t4.y);
        m4[i][1] = lse2(p0 + t4.z, p1v + t4.w);
    }
    if (lane < 16) {
        #pragma unroll
        for (int i = 0; i < NB; ++i) { Mb[i][k4] = m4[i][0];  Mb[i][LN + k4] = m4[i][1]; }
    }
    #pragma unroll
    for (int i = 0; i < NB; ++i) {
        l4[i][0] = e4[i][0] + m4[i][0];  l4[i][1] = e4[i][1] + m4[i][1];
    }

    // ---------------- level 5 (up to 64 leaves) ------------------------------
    const int s5a = lane >> 2;
    const int s5b = 8 + (lane >> 2);
    #pragma unroll
    for (int i = 0; i < NB; ++i) {
        float x0 = __shfl_sync(0xffffffffu, l4[i][0], s5a);
        float x1 = __shfl_sync(0xffffffffu, l4[i][1], s5a);
        float y0 = __shfl_sync(0xffffffffu, l4[i][0], s5b);
        float y1 = __shfl_sync(0xffffffffu, l4[i][1], s5b);
        if (va) {
            float u0 = lse2(x0 + t5a.x, x1 + t5a.y);
            float u1 = lse2(x0 + t5a.z, x1 + t5a.w);
            Mb[i][k5a] = u0;  Mb[i][LN + k5a] = u1;      // coalesced
        }
        if (vb) {
            float u0 = lse2(y0 + t5b.x, y1 + t5b.y);
            float u1 = lse2(y0 + t5b.z, y1 + t5b.w);
            Mb[i][k5b] = u0;  Mb[i][LN + k5b] = u1;
        }
    }
}

extern "C" void kernel_launch(void* const* d_in, const int* in_sizes, int n_in,
                              void* d_out, int out_size) {
    const float* E = (const float*)d_in[0];   // emissions   [B, C, L] f32
    const float* T = (const float*)d_in[1];   // transitions [L, L, C, C] f32
    float* M = (float*)d_out;                 // messages    [B, C, L] f32

    dim3 grid(64, 2);                         // 64 subtrees x 2 groups of 8x4 batches
    k_all<<<grid, 256>>>(E, T, M);
}